// round 5
// baseline (speedup 1.0000x reference)
#include <cuda_runtime.h>

#define BATCH 16384

typedef unsigned long long u64;
typedef unsigned int       u32;

// Scratch (device globals: allocation-free rule)
__device__ float  g_xT[64 * BATCH];     // x transposed [i][b]
__device__ float  g_hT[64 * BATCH];     // layer0 output transposed [o][b]
__device__ float4 g_dup0[4096 * 6];     // layer0 params, duplicated (w,w) pairs
__device__ float4 g_dup1[1024 * 6];     // layer1 params, duplicated pairs
__device__ float  g_b3s0[64];           // sum_i b3 per output o, layer0
__device__ float  g_b3s1[16];           // layer1

__device__ __forceinline__ u64 fma2(u64 a, u64 b, u64 c) {
    u64 d;
    asm("fma.rn.f32x2 %0, %1, %2, %3;" : "=l"(d) : "l"(a), "l"(b), "l"(c));
    return d;
}
__device__ __forceinline__ u64 pk(float a, float b) {
    return (u64)__float_as_uint(a) | ((u64)__float_as_uint(b) << 32);
}
__device__ __forceinline__ float flo(u64 v) { return __uint_as_float((u32)v); }
__device__ __forceinline__ float fhi(u64 v) { return __uint_as_float((u32)(v >> 32)); }
__device__ __forceinline__ u64 relu2(u64 v) {
    return pk(fmaxf(flo(v), 0.0f), fmaxf(fhi(v), 0.0f));
}

// Fused prep: blocks 0..19 param duplication (5120 subnets, 1 thread each),
// blocks 20..29 b3 column sums (80 warps), blocks 30..285 x transpose tiles.
__global__ __launch_bounds__(256) void prep(
    const float* __restrict__ x,
    const float* __restrict__ l0W1, const float* __restrict__ l0b1,
    const float* __restrict__ l0W2, const float* __restrict__ l0b2,
    const float* __restrict__ l0W3, const float* __restrict__ l0b3,
    const float* __restrict__ l1W1, const float* __restrict__ l1b1,
    const float* __restrict__ l1W2, const float* __restrict__ l1b2,
    const float* __restrict__ l1W3, const float* __restrict__ l1b3)
{
    __shared__ float ts[64 * 65];
    int blk = blockIdx.x, tid = threadIdx.x;

    if (blk < 20) {
        int t = blk * 256 + tid;             // 0..5119
        bool isL0 = t < 4096;
        int n = isL0 ? t : t - 4096;
        const float* W1 = isL0 ? l0W1 : l1W1;
        const float* b1 = isL0 ? l0b1 : l1b1;
        const float* W2 = isL0 ? l0W2 : l1W2;
        const float* b2 = isL0 ? l0b2 : l1b2;
        const float* W3 = isL0 ? l0W3 : l1W3;
        float4* q = (isL0 ? g_dup0 : g_dup1) + (size_t)n * 6;
        float w1a = W1[2*n], w1b = W1[2*n+1];
        float b1a = b1[2*n], b1b = b1[2*n+1];
        float w200 = W2[4*n], w201 = W2[4*n+1], w210 = W2[4*n+2], w211 = W2[4*n+3];
        float b2a = b2[2*n], b2b = b2[2*n+1];
        float w3a = W3[2*n], w3b = W3[2*n+1];
        q[0] = make_float4(w1a, w1a, w1b, w1b);
        q[1] = make_float4(b1a, b1a, b1b, b1b);
        q[2] = make_float4(w200, w200, w201, w201);
        q[3] = make_float4(w210, w210, w211, w211);
        q[4] = make_float4(b2a, b2a, b2b, b2b);
        q[5] = make_float4(w3a, w3a, w3b, w3b);
    } else if (blk < 30) {
        int wg = (blk - 20) * 8 + (tid >> 5);   // 0..79
        int lane = tid & 31;
        bool isL0 = wg < 64;
        int o = isL0 ? wg : wg - 64;
        int OUT = isL0 ? 64 : 16;
        const float* b3 = isL0 ? l0b3 : l1b3;
        float s = b3[lane * OUT + o] + b3[(lane + 32) * OUT + o];
#pragma unroll
        for (int m = 16; m; m >>= 1) s += __shfl_xor_sync(0xffffffffu, s, m);
        if (lane == 0) (isL0 ? g_b3s0 : g_b3s1)[o] = s;
    } else {
        // Transpose one 64b x 64i tile of x into g_xT, fully vectorized.
        int B0 = (blk - 30) * 64;
        int i4 = tid & 15, brow = tid >> 4;      // 16 b-rows per pass
#pragma unroll
        for (int p = 0; p < 4; p++) {
            int b = p * 16 + brow;
            float4 v = *(const float4*)&x[(size_t)(B0 + b) * 64 + i4 * 4];
            ts[(i4 * 4 + 0) * 65 + b] = v.x;
            ts[(i4 * 4 + 1) * 65 + b] = v.y;
            ts[(i4 * 4 + 2) * 65 + b] = v.z;
            ts[(i4 * 4 + 3) * 65 + b] = v.w;
        }
        __syncthreads();
        int i = tid & 63, bq0 = tid >> 6;        // 4 b-quads per pass
#pragma unroll
        for (int p = 0; p < 4; p++) {
            int b = (p * 4 + bq0) * 4;
            float4 w = make_float4(ts[i * 65 + b],     ts[i * 65 + b + 1],
                                   ts[i * 65 + b + 2], ts[i * 65 + b + 3]);
            *(float4*)&g_xT[(size_t)i * BATCH + B0 + b] = w;
        }
    }
}

// One KAN layer. 256 threads = 8 warps; warp w owns output column o = o0+w.
// Each lane processes 8 batch elements (4 f32x2 streams) -> warp-iter covers
// 256 evals with only 6 uniform LDG.128 (params) + 4 coalesced LDG.64 (x).
// MODE 0: g_xT -> g_hT (transposed). MODE 1: g_hT -> dout [b][OUT].
template <int OUT, int MODE>
__global__ __launch_bounds__(256) void kan_layer(float* __restrict__ dout)
{
    int tid  = threadIdx.x;
    int lane = tid & 31;
    int o    = blockIdx.y * 8 + (tid >> 5);
    int b    = blockIdx.x * 256 + lane * 8;

    const float* src = (MODE == 0) ? g_xT : g_hT;
    const ulonglong2* q =
        (const ulonglong2*)(((MODE == 0) ? g_dup0 : g_dup1) + (size_t)o * 6);
    float s3 = ((MODE == 0) ? g_b3s0 : g_b3s1)[o];
    u64 sp = pk(s3, s3);

    u64 acc0 = sp, acc1 = sp, acc2 = sp, acc3 = sp;
    const float* xb = src + b;

#pragma unroll 1
    for (int i = 0; i < 64; i++) {
        ulonglong2 p0 = q[0], p1 = q[1], p2 = q[2], p3 = q[3], p4 = q[4], p5 = q[5];
        const u64* xp = (const u64*)(xb + (size_t)i * BATCH);
        u64 xv0 = xp[0], xv1 = xp[1], xv2 = xp[2], xv3 = xp[3];

        u64 r1, r2, ga, gb;
        r1 = relu2(fma2(p0.x, xv0, p1.x));
        r2 = relu2(fma2(p0.y, xv0, p1.y));
        ga = relu2(fma2(p2.x, r1, fma2(p2.y, r2, p4.x)));
        gb = relu2(fma2(p3.x, r1, fma2(p3.y, r2, p4.y)));
        acc0 = fma2(p5.y, gb, fma2(p5.x, ga, acc0));

        r1 = relu2(fma2(p0.x, xv1, p1.x));
        r2 = relu2(fma2(p0.y, xv1, p1.y));
        ga = relu2(fma2(p2.x, r1, fma2(p2.y, r2, p4.x)));
        gb = relu2(fma2(p3.x, r1, fma2(p3.y, r2, p4.y)));
        acc1 = fma2(p5.y, gb, fma2(p5.x, ga, acc1));

        r1 = relu2(fma2(p0.x, xv2, p1.x));
        r2 = relu2(fma2(p0.y, xv2, p1.y));
        ga = relu2(fma2(p2.x, r1, fma2(p2.y, r2, p4.x)));
        gb = relu2(fma2(p3.x, r1, fma2(p3.y, r2, p4.y)));
        acc2 = fma2(p5.y, gb, fma2(p5.x, ga, acc2));

        r1 = relu2(fma2(p0.x, xv3, p1.x));
        r2 = relu2(fma2(p0.y, xv3, p1.y));
        ga = relu2(fma2(p2.x, r1, fma2(p2.y, r2, p4.x)));
        gb = relu2(fma2(p3.x, r1, fma2(p3.y, r2, p4.y)));
        acc3 = fma2(p5.y, gb, fma2(p5.x, ga, acc3));

        q += OUT * 6;   // next i: subnet n = i*OUT + o (6 ulonglong2 per subnet)
    }

    if (MODE == 0) {
        u64* dst = (u64*)&g_hT[(size_t)o * BATCH + b];
        dst[0] = acc0; dst[1] = acc1; dst[2] = acc2; dst[3] = acc3;
    } else {
        dout[(size_t)(b + 0) * OUT + o] = flo(acc0);
        dout[(size_t)(b + 1) * OUT + o] = fhi(acc0);
        dout[(size_t)(b + 2) * OUT + o] = flo(acc1);
        dout[(size_t)(b + 3) * OUT + o] = fhi(acc1);
        dout[(size_t)(b + 4) * OUT + o] = flo(acc2);
        dout[(size_t)(b + 5) * OUT + o] = fhi(acc2);
        dout[(size_t)(b + 6) * OUT + o] = flo(acc3);
        dout[(size_t)(b + 7) * OUT + o] = fhi(acc3);
    }
}

extern "C" void kernel_launch(void* const* d_in, const int* in_sizes, int n_in,
                              void* d_out, int out_size)
{
    const float* x    = (const float*)d_in[0];
    const float* l0W1 = (const float*)d_in[1];
    const float* l0b1 = (const float*)d_in[2];
    const float* l0W2 = (const float*)d_in[3];
    const float* l0b2 = (const float*)d_in[4];
    const float* l0W3 = (const float*)d_in[5];
    const float* l0b3 = (const float*)d_in[6];
    const float* l1W1 = (const float*)d_in[7];
    const float* l1b1 = (const float*)d_in[8];
    const float* l1W2 = (const float*)d_in[9];
    const float* l1b2 = (const float*)d_in[10];
    const float* l1W3 = (const float*)d_in[11];
    const float* l1b3 = (const float*)d_in[12];
    float* out = (float*)d_out;

    prep<<<286, 256>>>(x, l0W1, l0b1, l0W2, l0b2, l0W3, l0b3,
                          l1W1, l1b1, l1W2, l1b2, l1W3, l1b3);
    kan_layer<64, 0><<<dim3(BATCH / 256, 8), 256>>>(nullptr);
    kan_layer<16, 1><<<dim3(BATCH / 256, 2), 256>>>(out);
}

// round 6
// speedup vs baseline: 2.3900x; 2.3900x over previous
#include <cuda_runtime.h>

#define BATCH 16384

typedef unsigned long long u64;
typedef unsigned int       u32;

// Scratch (device globals: allocation-free rule)
__device__ float  g_xT[64 * BATCH];     // x transposed [i][b]
__device__ float  g_hT[64 * BATCH];     // layer0 output transposed [o][b]
__device__ float4 g_dup0[4096 * 6];     // layer0 params, duplicated (w,w) pairs
__device__ float4 g_dup1[1024 * 6];     // layer1 params, duplicated pairs
__device__ float  g_b3s0[64];           // sum_i b3 per output o, layer0
__device__ float  g_b3s1[16];           // layer1

__device__ __forceinline__ u64 fma2(u64 a, u64 b, u64 c) {
    u64 d;
    asm("fma.rn.f32x2 %0, %1, %2, %3;" : "=l"(d) : "l"(a), "l"(b), "l"(c));
    return d;
}
__device__ __forceinline__ u64 pk(float a, float b) {
    return (u64)__float_as_uint(a) | ((u64)__float_as_uint(b) << 32);
}
__device__ __forceinline__ float flo(u64 v) { return __uint_as_float((u32)v); }
__device__ __forceinline__ float fhi(u64 v) { return __uint_as_float((u32)(v >> 32)); }
__device__ __forceinline__ u64 relu2(u64 v) {
    return pk(fmaxf(flo(v), 0.0f), fmaxf(fhi(v), 0.0f));
}

// Fused prep: blocks 0..19 param duplication (5120 subnets, 1 thread each),
// blocks 20..29 b3 column sums (80 warps), blocks 30..285 x transpose tiles.
__global__ __launch_bounds__(256) void prep(
    const float* __restrict__ x,
    const float* __restrict__ l0W1, const float* __restrict__ l0b1,
    const float* __restrict__ l0W2, const float* __restrict__ l0b2,
    const float* __restrict__ l0W3, const float* __restrict__ l0b3,
    const float* __restrict__ l1W1, const float* __restrict__ l1b1,
    const float* __restrict__ l1W2, const float* __restrict__ l1b2,
    const float* __restrict__ l1W3, const float* __restrict__ l1b3)
{
    __shared__ float ts[64 * 65];
    int blk = blockIdx.x, tid = threadIdx.x;

    if (blk < 20) {
        int t = blk * 256 + tid;             // 0..5119
        bool isL0 = t < 4096;
        int n = isL0 ? t : t - 4096;
        const float* W1 = isL0 ? l0W1 : l1W1;
        const float* b1 = isL0 ? l0b1 : l1b1;
        const float* W2 = isL0 ? l0W2 : l1W2;
        const float* b2 = isL0 ? l0b2 : l1b2;
        const float* W3 = isL0 ? l0W3 : l1W3;
        float4* q = (isL0 ? g_dup0 : g_dup1) + (size_t)n * 6;
        float w1a = W1[2*n], w1b = W1[2*n+1];
        float b1a = b1[2*n], b1b = b1[2*n+1];
        float w200 = W2[4*n], w201 = W2[4*n+1], w210 = W2[4*n+2], w211 = W2[4*n+3];
        float b2a = b2[2*n], b2b = b2[2*n+1];
        float w3a = W3[2*n], w3b = W3[2*n+1];
        q[0] = make_float4(w1a, w1a, w1b, w1b);
        q[1] = make_float4(b1a, b1a, b1b, b1b);
        q[2] = make_float4(w200, w200, w201, w201);
        q[3] = make_float4(w210, w210, w211, w211);
        q[4] = make_float4(b2a, b2a, b2b, b2b);
        q[5] = make_float4(w3a, w3a, w3b, w3b);
    } else if (blk < 30) {
        int wg = (blk - 20) * 8 + (tid >> 5);   // 0..79
        int lane = tid & 31;
        bool isL0 = wg < 64;
        int o = isL0 ? wg : wg - 64;
        int OUT = isL0 ? 64 : 16;
        const float* b3 = isL0 ? l0b3 : l1b3;
        float s = b3[lane * OUT + o] + b3[(lane + 32) * OUT + o];
#pragma unroll
        for (int m = 16; m; m >>= 1) s += __shfl_xor_sync(0xffffffffu, s, m);
        if (lane == 0) (isL0 ? g_b3s0 : g_b3s1)[o] = s;
    } else {
        // Transpose one 64b x 64i tile of x into g_xT, fully vectorized.
        int B0 = (blk - 30) * 64;
        int i4 = tid & 15, brow = tid >> 4;      // 16 b-rows per pass
#pragma unroll
        for (int p = 0; p < 4; p++) {
            int b = p * 16 + brow;
            float4 v = *(const float4*)&x[(size_t)(B0 + b) * 64 + i4 * 4];
            ts[(i4 * 4 + 0) * 65 + b] = v.x;
            ts[(i4 * 4 + 1) * 65 + b] = v.y;
            ts[(i4 * 4 + 2) * 65 + b] = v.z;
            ts[(i4 * 4 + 3) * 65 + b] = v.w;
        }
        __syncthreads();
        int i = tid & 63, bq0 = tid >> 6;        // 4 b-quads per pass
#pragma unroll
        for (int p = 0; p < 4; p++) {
            int b = (p * 4 + bq0) * 4;
            float4 w = make_float4(ts[i * 65 + b],     ts[i * 65 + b + 1],
                                   ts[i * 65 + b + 2], ts[i * 65 + b + 3]);
            *(float4*)&g_xT[(size_t)i * BATCH + B0 + b] = w;
        }
    }
}

// One KAN layer. 256 threads = 8 warps; warp ol owns output column o = o0+ol.
// Lane handles 8 batch elements as 4 f32x2 streams, loaded as 4 x LDG.64 with
// 8-byte lane stride (each load spans 256B = 2 L1 wavefronts). Params for the
// CTA's 8 o-columns are staged once into smem (float4-vectorized copy from the
// pre-duplicated g_dup buffer) and read in-loop as 6 uniform LDS.128 per
// (i,o) — broadcast, no L1tex traffic.
// MODE 0: g_xT -> g_hT (transposed rows). MODE 1: g_hT -> dout [b][OUT].
template <int OUT, int MODE>
__global__ __launch_bounds__(256) void kan_layer(float* __restrict__ dout)
{
    __shared__ float4 sp4[64 * 8 * 6];   // 48KB: [i][ol][6]

    int tid  = threadIdx.x;
    int lane = tid & 31;
    int ol   = tid >> 5;
    int o0   = blockIdx.y * 8;
    int o    = o0 + ol;
    int B0   = blockIdx.x * 256;

    // Stage params: for each i, the 8 subnets n = i*OUT + o0 .. +7 occupy 48
    // contiguous float4 in g_dup -> one flat coalesced copy.
    const float4* dup = ((MODE == 0) ? g_dup0 : g_dup1);
#pragma unroll
    for (int s = tid; s < 3072; s += 256) {
        int i = s / 48;
        int r = s - i * 48;
        sp4[s] = dup[(size_t)(i * OUT + o0) * 6 + r];
    }

    float s3 = ((MODE == 0) ? g_b3s0 : g_b3s1)[o];
    __syncthreads();

    const float* src  = (MODE == 0) ? g_xT : g_hT;
    const float* xrow = src + B0 + lane * 2;
    const ulonglong2* pb = ((const ulonglong2*)sp4) + ol * 6;

    u64 sp_ = pk(s3, s3);
    u64 acc0 = sp_, acc1 = sp_, acc2 = sp_, acc3 = sp_;

#pragma unroll 2
    for (int i = 0; i < 64; i++) {
        const ulonglong2* q = pb + i * 48;
        ulonglong2 p0 = q[0], p1 = q[1], p2 = q[2], p3 = q[3], p4 = q[4], p5 = q[5];
        const float* xr = xrow + (size_t)i * BATCH;
        u64 xv0 = *(const u64*)(xr);
        u64 xv1 = *(const u64*)(xr + 64);
        u64 xv2 = *(const u64*)(xr + 128);
        u64 xv3 = *(const u64*)(xr + 192);

        u64 r1, r2, ga, gb;
        r1 = relu2(fma2(p0.x, xv0, p1.x));
        r2 = relu2(fma2(p0.y, xv0, p1.y));
        ga = relu2(fma2(p2.x, r1, fma2(p2.y, r2, p4.x)));
        gb = relu2(fma2(p3.x, r1, fma2(p3.y, r2, p4.y)));
        acc0 = fma2(p5.y, gb, fma2(p5.x, ga, acc0));

        r1 = relu2(fma2(p0.x, xv1, p1.x));
        r2 = relu2(fma2(p0.y, xv1, p1.y));
        ga = relu2(fma2(p2.x, r1, fma2(p2.y, r2, p4.x)));
        gb = relu2(fma2(p3.x, r1, fma2(p3.y, r2, p4.y)));
        acc1 = fma2(p5.y, gb, fma2(p5.x, ga, acc1));

        r1 = relu2(fma2(p0.x, xv2, p1.x));
        r2 = relu2(fma2(p0.y, xv2, p1.y));
        ga = relu2(fma2(p2.x, r1, fma2(p2.y, r2, p4.x)));
        gb = relu2(fma2(p3.x, r1, fma2(p3.y, r2, p4.y)));
        acc2 = fma2(p5.y, gb, fma2(p5.x, ga, acc2));

        r1 = relu2(fma2(p0.x, xv3, p1.x));
        r2 = relu2(fma2(p0.y, xv3, p1.y));
        ga = relu2(fma2(p2.x, r1, fma2(p2.y, r2, p4.x)));
        gb = relu2(fma2(p3.x, r1, fma2(p3.y, r2, p4.y)));
        acc3 = fma2(p5.y, gb, fma2(p5.x, ga, acc3));
    }

    if (MODE == 0) {
        float* row = g_hT + (size_t)o * BATCH + B0 + lane * 2;
        *(u64*)(row)       = acc0;
        *(u64*)(row + 64)  = acc1;
        *(u64*)(row + 128) = acc2;
        *(u64*)(row + 192) = acc3;
    } else {
        int b = B0 + lane * 2;
        dout[(size_t)(b + 0)   * OUT + o] = flo(acc0);
        dout[(size_t)(b + 1)   * OUT + o] = fhi(acc0);
        dout[(size_t)(b + 64)  * OUT + o] = flo(acc1);
        dout[(size_t)(b + 65)  * OUT + o] = fhi(acc1);
        dout[(size_t)(b + 128) * OUT + o] = flo(acc2);
        dout[(size_t)(b + 129) * OUT + o] = fhi(acc2);
        dout[(size_t)(b + 192) * OUT + o] = flo(acc3);
        dout[(size_t)(b + 193) * OUT + o] = fhi(acc3);
    }
}

extern "C" void kernel_launch(void* const* d_in, const int* in_sizes, int n_in,
                              void* d_out, int out_size)
{
    const float* x    = (const float*)d_in[0];
    const float* l0W1 = (const float*)d_in[1];
    const float* l0b1 = (const float*)d_in[2];
    const float* l0W2 = (const float*)d_in[3];
    const float* l0b2 = (const float*)d_in[4];
    const float* l0W3 = (const float*)d_in[5];
    const float* l0b3 = (const float*)d_in[6];
    const float* l1W1 = (const float*)d_in[7];
    const float* l1b1 = (const float*)d_in[8];
    const float* l1W2 = (const float*)d_in[9];
    const float* l1b2 = (const float*)d_in[10];
    const float* l1W3 = (const float*)d_in[11];
    const float* l1b3 = (const float*)d_in[12];
    float* out = (float*)d_out;

    prep<<<286, 256>>>(x, l0W1, l0b1, l0W2, l0b2, l0W3, l0b3,
                          l1W1, l1b1, l1W2, l1b2, l1W3, l1b3);
    kan_layer<64, 0><<<dim3(BATCH / 256, 8), 256>>>(nullptr);
    kan_layer<16, 1><<<dim3(BATCH / 256, 2), 256>>>(out);
}